// round 1
// baseline (speedup 1.0000x reference)
#include <cuda_runtime.h>
#include <cuda_bf16.h>
#include <cstdint>

// Problem shape (fixed by the dataset)
#define NN 50000     // nodes
#define KK 256       // in feats
#define MM 128       // out feats
#define EE 800000    // edges

// Scratch for hw = h @ W  (25.6 MB) — static __device__ array (no allocs allowed)
__device__ float g_hw[(size_t)NN * MM];

// ---------------------------------------------------------------------------
// Kernel 1: hw = h @ W   (fp32, W resident in SMEM, 4 rows x 4 cols per thread)
// block: 512 threads (16 warps), each warp computes 4 rows x 128 cols
// grid: ceil(N / 64)
// ---------------------------------------------------------------------------
__global__ __launch_bounds__(512, 1)
void gemm_kernel(const float* __restrict__ h, const float* __restrict__ W) {
    extern __shared__ float Ws[];  // 256*128 floats = 128 KB

    // cooperative load of W into smem (vectorized)
    {
        const float4* Wv = (const float4*)W;
        float4* Sv = (float4*)Ws;
        #pragma unroll
        for (int i = threadIdx.x; i < (KK * MM) / 4; i += 512) {
            Sv[i] = Wv[i];
        }
    }
    __syncthreads();

    const int warp = threadIdx.x >> 5;
    const int lane = threadIdx.x & 31;
    const int row0 = blockIdx.x * 64 + warp * 4;
    if (row0 >= NN) return;

    // accumulators: 4 rows x (2 float2 column pairs) = 16 outputs/thread
    float2 acc[4][2];
    #pragma unroll
    for (int r = 0; r < 4; r++) {
        acc[r][0] = make_float2(0.f, 0.f);
        acc[r][1] = make_float2(0.f, 0.f);
    }

    const float2* __restrict__ Ws2 = (const float2*)Ws;

    // per-row h pointers (clamped; invalid rows computed but not stored)
    const float4* hp[4];
    #pragma unroll
    for (int r = 0; r < 4; r++) {
        int row = row0 + r;
        if (row >= NN) row = NN - 1;
        hp[r] = (const float4*)(h + (size_t)row * KK);
    }

    #pragma unroll 4
    for (int k4 = 0; k4 < KK / 4; k4++) {
        float4 hv[4];
        #pragma unroll
        for (int r = 0; r < 4; r++) hv[r] = hp[r][k4];  // broadcast loads (same addr per warp)

        #pragma unroll
        for (int kk = 0; kk < 4; kk++) {
            const int k = k4 * 4 + kk;
            // W[k][2*lane .. 2*lane+1] and W[k][64+2*lane .. 64+2*lane+1]
            const float2 w0 = Ws2[k * 64 + lane];
            const float2 w1 = Ws2[k * 64 + 32 + lane];
            #pragma unroll
            for (int r = 0; r < 4; r++) {
                const float s = (kk == 0) ? hv[r].x : (kk == 1) ? hv[r].y
                              : (kk == 2) ? hv[r].z : hv[r].w;
                acc[r][0].x = fmaf(s, w0.x, acc[r][0].x);
                acc[r][0].y = fmaf(s, w0.y, acc[r][0].y);
                acc[r][1].x = fmaf(s, w1.x, acc[r][1].x);
                acc[r][1].y = fmaf(s, w1.y, acc[r][1].y);
            }
        }
    }

    #pragma unroll
    for (int r = 0; r < 4; r++) {
        const int row = row0 + r;
        if (row < NN) {
            float2* o = (float2*)(g_hw + (size_t)row * MM);
            o[lane]      = acc[r][0];  // cols 2*lane, 2*lane+1
            o[32 + lane] = acc[r][1];  // cols 64+2*lane, 64+2*lane+1
        }
    }
}

// ---------------------------------------------------------------------------
// Kernel 2: out[i][j] = b[j]   (seed output with bias before atomic scatter)
// ---------------------------------------------------------------------------
__global__ void init_bias_kernel(float* __restrict__ out, const float* __restrict__ b) {
    const int total = NN * MM / 4;  // float4 elements
    int i = blockIdx.x * blockDim.x + threadIdx.x;
    if (i >= total) return;
    const float4 bv = ((const float4*)b)[i & (MM / 4 - 1)];
    ((float4*)out)[i] = bv;
}

// ---------------------------------------------------------------------------
// Kernel 3: one warp per edge: out[dst] += hw[src]  (vector fp32 reduction)
// ---------------------------------------------------------------------------
__global__ __launch_bounds__(256)
void scatter_kernel(const int* __restrict__ src, const int* __restrict__ dst,
                    float* __restrict__ out, int E) {
    const int e = (int)((blockIdx.x * (unsigned)blockDim.x + threadIdx.x) >> 5);
    if (e >= E) return;
    const int lane = threadIdx.x & 31;

    const int s = __ldg(src + e);
    const int d = __ldg(dst + e);

    const float4 v = *(const float4*)(g_hw + (size_t)s * MM + lane * 4);
    float* p = out + (size_t)d * MM + lane * 4;

    // vectorized no-return global reduction (sm_90+): 1 RED.128 per lane
    asm volatile("red.global.add.v4.f32 [%0], {%1, %2, %3, %4};"
                 :: "l"(p), "f"(v.x), "f"(v.y), "f"(v.z), "f"(v.w)
                 : "memory");
}

// ---------------------------------------------------------------------------
// Kernel 4: in-place ReLU
// ---------------------------------------------------------------------------
__global__ void relu_kernel(float* __restrict__ out) {
    const int total = NN * MM / 4;
    int i = blockIdx.x * blockDim.x + threadIdx.x;
    if (i >= total) return;
    float4 v = ((float4*)out)[i];
    v.x = fmaxf(v.x, 0.f);
    v.y = fmaxf(v.y, 0.f);
    v.z = fmaxf(v.z, 0.f);
    v.w = fmaxf(v.w, 0.f);
    ((float4*)out)[i] = v;
}

// ---------------------------------------------------------------------------
// Launch: h, W, b, src, dst  ->  out [N, 128] fp32
// ---------------------------------------------------------------------------
extern "C" void kernel_launch(void* const* d_in, const int* in_sizes, int n_in,
                              void* d_out, int out_size) {
    const float* h = (const float*)d_in[0];
    const float* W = (const float*)d_in[1];
    const float* b = (const float*)d_in[2];
    const int* src = (const int*)d_in[3];
    const int* dst = (const int*)d_in[4];
    float* out = (float*)d_out;

    const int E = in_sizes[3];

    // 128 KB dynamic smem for W (exceeds 48 KB default) — idempotent, host-side
    static bool attr_set = false;
    if (!attr_set) {
        cudaFuncSetAttribute(gemm_kernel,
                             cudaFuncAttributeMaxDynamicSharedMemorySize,
                             KK * MM * (int)sizeof(float));
        attr_set = true;
    }

    // 1) hw = h @ W
    {
        const int blocks = (NN + 63) / 64;
        gemm_kernel<<<blocks, 512, KK * MM * sizeof(float)>>>(h, W);
    }
    // 2) out = b (broadcast)
    {
        const int total = NN * MM / 4;
        init_bias_kernel<<<(total + 255) / 256, 256>>>(out, b);
    }
    // 3) out[dst] += hw[src], one warp per edge
    {
        const long long threads = (long long)E * 32;
        const int blocks = (int)((threads + 255) / 256);
        scatter_kernel<<<blocks, 256>>>(src, dst, out, E);
    }
    // 4) relu in place
    {
        const int total = NN * MM / 4;
        relu_kernel<<<(total + 255) / 256, 256>>>(out);
    }
}

// round 2
// speedup vs baseline: 1.2506x; 1.2506x over previous
#include <cuda_runtime.h>
#include <cuda_bf16.h>
#include <cstdint>

// Problem shape (fixed by the dataset)
#define NN 50000     // nodes
#define KK 256       // in feats
#define MM 128       // out feats
#define EE 800000    // edges

#define SCAN_B 512
#define NB_SCAN ((NN + SCAN_B - 1) / SCAN_B)   // 98

// Static scratch (no allocs allowed)
__device__ float g_hw[(size_t)NN * MM];   // h @ W           (25.6 MB)
__device__ int   g_cnt[NN];               // degree histogram
__device__ int   g_off[NN];               // CSR exclusive offsets
__device__ int   g_pos[NN];               // fill cursors
__device__ int   g_bsum[NB_SCAN + 32];    // scan block sums
__device__ int   g_srcs[EE];              // src ids grouped by dst

// ---------------------------------------------------------------------------
// Kernel 1: hw = h @ W   (fp32, W resident in SMEM, 4 rows x 4 cols per thread)
// ---------------------------------------------------------------------------
__global__ __launch_bounds__(512, 1)
void gemm_kernel(const float* __restrict__ h, const float* __restrict__ W) {
    extern __shared__ float Ws[];  // 256*128 floats = 128 KB

    {
        const float4* Wv = (const float4*)W;
        float4* Sv = (float4*)Ws;
        #pragma unroll
        for (int i = threadIdx.x; i < (KK * MM) / 4; i += 512) {
            Sv[i] = Wv[i];
        }
    }
    __syncthreads();

    const int warp = threadIdx.x >> 5;
    const int lane = threadIdx.x & 31;
    const int row0 = blockIdx.x * 64 + warp * 4;
    if (row0 >= NN) return;

    float2 acc[4][2];
    #pragma unroll
    for (int r = 0; r < 4; r++) {
        acc[r][0] = make_float2(0.f, 0.f);
        acc[r][1] = make_float2(0.f, 0.f);
    }

    const float2* __restrict__ Ws2 = (const float2*)Ws;

    const float4* hp[4];
    #pragma unroll
    for (int r = 0; r < 4; r++) {
        int row = row0 + r;
        if (row >= NN) row = NN - 1;
        hp[r] = (const float4*)(h + (size_t)row * KK);
    }

    #pragma unroll 4
    for (int k4 = 0; k4 < KK / 4; k4++) {
        float4 hv[4];
        #pragma unroll
        for (int r = 0; r < 4; r++) hv[r] = hp[r][k4];

        #pragma unroll
        for (int kk = 0; kk < 4; kk++) {
            const int k = k4 * 4 + kk;
            const float2 w0 = Ws2[k * 64 + lane];
            const float2 w1 = Ws2[k * 64 + 32 + lane];
            #pragma unroll
            for (int r = 0; r < 4; r++) {
                const float s = (kk == 0) ? hv[r].x : (kk == 1) ? hv[r].y
                              : (kk == 2) ? hv[r].z : hv[r].w;
                acc[r][0].x = fmaf(s, w0.x, acc[r][0].x);
                acc[r][0].y = fmaf(s, w0.y, acc[r][0].y);
                acc[r][1].x = fmaf(s, w1.x, acc[r][1].x);
                acc[r][1].y = fmaf(s, w1.y, acc[r][1].y);
            }
        }
    }

    #pragma unroll
    for (int r = 0; r < 4; r++) {
        const int row = row0 + r;
        if (row < NN) {
            float2* o = (float2*)(g_hw + (size_t)row * MM);
            o[lane]      = acc[r][0];
            o[32 + lane] = acc[r][1];
        }
    }
}

// ---------------------------------------------------------------------------
// CSR build kernels
// ---------------------------------------------------------------------------
__global__ void zero_cnt_kernel() {
    int i = blockIdx.x * blockDim.x + threadIdx.x;
    if (i < NN) g_cnt[i] = 0;
}

__global__ void hist_kernel(const int* __restrict__ dst, int E) {
    int e = blockIdx.x * blockDim.x + threadIdx.x;
    if (e < E) atomicAdd(&g_cnt[dst[e]], 1);
}

// block-local exclusive scan of 512 counts; write block total
__global__ __launch_bounds__(SCAN_B)
void scan1_kernel() {
    __shared__ int sdata[SCAN_B];
    const int t = threadIdx.x;
    const int i = blockIdx.x * SCAN_B + t;
    const int v = (i < NN) ? g_cnt[i] : 0;
    sdata[t] = v;
    __syncthreads();
    #pragma unroll
    for (int off = 1; off < SCAN_B; off <<= 1) {
        int x = (t >= off) ? sdata[t - off] : 0;
        __syncthreads();
        sdata[t] += x;
        __syncthreads();
    }
    if (i < NN) g_off[i] = sdata[t] - v;   // exclusive
    if (t == SCAN_B - 1) g_bsum[blockIdx.x] = sdata[t];
}

// exclusive scan of NB_SCAN block sums (single block, smem-serial)
__global__ void scan2_kernel() {
    __shared__ int s[NB_SCAN];
    const int t = threadIdx.x;
    if (t < NB_SCAN) s[t] = g_bsum[t];
    __syncthreads();
    if (t == 0) {
        int run = 0;
        for (int b = 0; b < NB_SCAN; b++) { int v = s[b]; s[b] = run; run += v; }
    }
    __syncthreads();
    if (t < NB_SCAN) g_bsum[t] = s[t];
}

// add block offsets; init fill cursors
__global__ void scan3_kernel() {
    int i = blockIdx.x * blockDim.x + threadIdx.x;
    if (i < NN) {
        int o = g_off[i] + g_bsum[i >> 9];  // 512 = 2^9
        g_off[i] = o;
        g_pos[i] = o;
    }
}

__global__ void fill_kernel(const int* __restrict__ src, const int* __restrict__ dst, int E) {
    int e = blockIdx.x * blockDim.x + threadIdx.x;
    if (e < E) {
        int p = atomicAdd(&g_pos[dst[e]], 1);
        g_srcs[p] = src[e];
    }
}

// ---------------------------------------------------------------------------
// Segmented reduce: one warp per node. acc = sum over its srcs of hw[src];
// out = relu(acc + b). No atomics, fused epilogue.
// ---------------------------------------------------------------------------
__global__ __launch_bounds__(256)
void reduce_kernel(const float* __restrict__ b, float* __restrict__ out) {
    const int n = (int)((blockIdx.x * (unsigned)blockDim.x + threadIdx.x) >> 5);
    if (n >= NN) return;
    const int lane = threadIdx.x & 31;

    const int beg = g_off[n];
    const int deg = g_cnt[n];

    float4 acc = make_float4(0.f, 0.f, 0.f, 0.f);

    // software-pipelined gather: prefetch next src id & row pointer
    int s_next = (deg > 0) ? __ldg(&g_srcs[beg]) : 0;
    for (int i = 0; i < deg; i++) {
        const int s = s_next;
        if (i + 1 < deg) s_next = __ldg(&g_srcs[beg + i + 1]);
        const float4 v = __ldg((const float4*)(g_hw + (size_t)s * MM) + lane);
        acc.x += v.x; acc.y += v.y; acc.z += v.z; acc.w += v.w;
    }

    const float4 bv = __ldg((const float4*)b + lane);
    acc.x = fmaxf(acc.x + bv.x, 0.f);
    acc.y = fmaxf(acc.y + bv.y, 0.f);
    acc.z = fmaxf(acc.z + bv.z, 0.f);
    acc.w = fmaxf(acc.w + bv.w, 0.f);

    ((float4*)(out + (size_t)n * MM))[lane] = acc;
}

// ---------------------------------------------------------------------------
// Launch: h, W, b, src, dst  ->  out [N, 128] fp32
// ---------------------------------------------------------------------------
extern "C" void kernel_launch(void* const* d_in, const int* in_sizes, int n_in,
                              void* d_out, int out_size) {
    const float* h = (const float*)d_in[0];
    const float* W = (const float*)d_in[1];
    const float* b = (const float*)d_in[2];
    const int* src = (const int*)d_in[3];
    const int* dst = (const int*)d_in[4];
    float* out = (float*)d_out;

    const int E = in_sizes[3];

    static bool attr_set = false;
    if (!attr_set) {
        cudaFuncSetAttribute(gemm_kernel,
                             cudaFuncAttributeMaxDynamicSharedMemorySize,
                             KK * MM * (int)sizeof(float));
        attr_set = true;
    }

    // 1) hw = h @ W
    gemm_kernel<<<(NN + 63) / 64, 512, KK * MM * sizeof(float)>>>(h, W);

    // 2) CSR build
    zero_cnt_kernel<<<(NN + 255) / 256, 256>>>();
    hist_kernel<<<(E + 255) / 256, 256>>>(dst, E);
    scan1_kernel<<<NB_SCAN, SCAN_B>>>();
    scan2_kernel<<<1, 128>>>();
    scan3_kernel<<<(NN + 255) / 256, 256>>>();
    fill_kernel<<<(E + 255) / 256, 256>>>(src, dst, E);

    // 3) segmented reduce + bias + relu (one warp per node)
    {
        const long long threads = (long long)NN * 32;
        reduce_kernel<<<(int)((threads + 255) / 256), 256>>>(b, out);
    }
}

// round 3
// speedup vs baseline: 1.4590x; 1.1666x over previous
#include <cuda_runtime.h>
#include <cuda_fp16.h>
#include <cstdint>

typedef unsigned long long ull;

// Problem shape (fixed by the dataset)
#define NN 50000     // nodes
#define KK 256       // in feats
#define MM 128       // out feats
#define EE 800000    // edges

#define SCAN_B 512
#define NB_SCAN ((NN + SCAN_B - 1) / SCAN_B)   // 98

// Static scratch (no allocs allowed)
__device__ __half g_hw[(size_t)NN * MM];  // h @ W in fp16 (12.8 MB, L2-resident)
__device__ int   g_cnt[NN];               // degree histogram
__device__ int   g_off[NN];               // CSR exclusive offsets
__device__ int   g_pos[NN];               // fill cursors
__device__ int   g_bsum[NB_SCAN + 32];    // scan block sums
__device__ int   g_srcs[EE];              // src ids grouped by dst

// ---------------------------------------------------------------------------
// Kernel 1: hw = h @ W using packed fma.rn.f32x2 (2 K-steps per instruction).
// W staged in SMEM as K-pair-interleaved 64-bit values:
//   Wp[kp*128 + col] = (W[2kp][col], W[2kp+1][col])
// 16 warps x 8 rows = 128 rows/block; each thread owns 4 cols (c*32+lane).
// acc[r][c] is f32x2: lo accumulates even k, hi odd k; summed at the end.
// ---------------------------------------------------------------------------
__global__ __launch_bounds__(512, 1)
void gemm_kernel(const float* __restrict__ h, const float* __restrict__ W) {
    extern __shared__ ull Wp[];  // 128 kpairs * 128 cols * 8B = 128 KB

    // stage W into kpair-interleaved layout
    for (int idx = threadIdx.x; idx < 128 * 128; idx += 512) {
        const int kp = idx >> 7;
        const int col = idx & 127;
        const unsigned lo = __float_as_uint(W[(2 * kp) * MM + col]);
        const unsigned hi = __float_as_uint(W[(2 * kp + 1) * MM + col]);
        Wp[idx] = (ull)lo | ((ull)hi << 32);
    }
    __syncthreads();

    const int warp = threadIdx.x >> 5;
    const int lane = threadIdx.x & 31;
    const int row0 = blockIdx.x * 128 + warp * 8;
    if (row0 >= NN) return;

    ull acc[8][4];
    #pragma unroll
    for (int r = 0; r < 8; r++)
        #pragma unroll
        for (int c = 0; c < 4; c++) acc[r][c] = 0ull;  // (+0.f, +0.f)

    // per-row h pointers as ulonglong2 (each .x/.y is a packed float k-pair)
    const ulonglong2* hp[8];
    #pragma unroll
    for (int r = 0; r < 8; r++) {
        int row = row0 + r;
        if (row >= NN) row = NN - 1;
        hp[r] = (const ulonglong2*)(h + (size_t)row * KK);
    }

    #pragma unroll 2
    for (int k4 = 0; k4 < KK / 4; k4++) {      // 64 iters, 2 kpairs each
        ulonglong2 hv[8];
        #pragma unroll
        for (int r = 0; r < 8; r++) hv[r] = hp[r][k4];   // broadcast LDG.128

        #pragma unroll
        for (int p = 0; p < 2; p++) {
            const int kp = k4 * 2 + p;
            ull w[4];
            #pragma unroll
            for (int c = 0; c < 4; c++)
                w[c] = Wp[kp * 128 + c * 32 + lane];     // LDS.64, conflict-free
            #pragma unroll
            for (int r = 0; r < 8; r++) {
                const ull a = p ? hv[r].y : hv[r].x;
                #pragma unroll
                for (int c = 0; c < 4; c++) {
                    asm("fma.rn.f32x2 %0, %1, %2, %0;"
                        : "+l"(acc[r][c]) : "l"(a), "l"(w[c]));
                }
            }
        }
    }

    #pragma unroll
    for (int r = 0; r < 8; r++) {
        const int row = row0 + r;
        if (row < NN) {
            #pragma unroll
            for (int c = 0; c < 4; c++) {
                const float lo = __uint_as_float((unsigned)(acc[r][c] & 0xffffffffu));
                const float hi = __uint_as_float((unsigned)(acc[r][c] >> 32));
                g_hw[(size_t)row * MM + c * 32 + lane] = __float2half_rn(lo + hi);
            }
        }
    }
}

// ---------------------------------------------------------------------------
// CSR build kernels
// ---------------------------------------------------------------------------
__global__ void zero_cnt_kernel() {
    int i = blockIdx.x * blockDim.x + threadIdx.x;
    if (i < NN) g_cnt[i] = 0;
}

__global__ void hist_kernel(const int* __restrict__ dst, int E) {
    int e = blockIdx.x * blockDim.x + threadIdx.x;
    if (e < E) atomicAdd(&g_cnt[dst[e]], 1);
}

// warp-shuffle exclusive scan of 512 counts per block; write block total
__global__ __launch_bounds__(SCAN_B)
void scan1_kernel() {
    __shared__ int wsum[16];
    const int t = threadIdx.x;
    const int lane = t & 31;
    const int warp = t >> 5;
    const int i = blockIdx.x * SCAN_B + t;
    const int v = (i < NN) ? g_cnt[i] : 0;

    int x = v;  // inclusive within warp
    #pragma unroll
    for (int off = 1; off < 32; off <<= 1) {
        int y = __shfl_up_sync(0xffffffffu, x, off);
        if (lane >= off) x += y;
    }
    if (lane == 31) wsum[warp] = x;
    __syncthreads();
    if (warp == 0 && lane < 16) {
        int w = wsum[lane];
        int xw = w;
        #pragma unroll
        for (int off = 1; off < 16; off <<= 1) {
            int y = __shfl_up_sync(0xffffu, xw, off);
            if (lane >= off) xw += y;
        }
        wsum[lane] = xw - w;  // exclusive warp offsets
    }
    __syncthreads();
    const int base = wsum[warp];
    if (i < NN) g_off[i] = base + x - v;
    if (t == SCAN_B - 1) g_bsum[blockIdx.x] = base + x;
}

// exclusive scan of NB_SCAN (=98) block sums, 128 threads
__global__ __launch_bounds__(128)
void scan2_kernel() {
    __shared__ int wsum[4];
    const int t = threadIdx.x;
    const int lane = t & 31;
    const int warp = t >> 5;
    const int v = (t < NB_SCAN) ? g_bsum[t] : 0;

    int x = v;
    #pragma unroll
    for (int off = 1; off < 32; off <<= 1) {
        int y = __shfl_up_sync(0xffffffffu, x, off);
        if (lane >= off) x += y;
    }
    if (lane == 31) wsum[warp] = x;
    __syncthreads();
    if (warp == 0 && lane < 4) {
        int w = wsum[lane];
        int xw = w;
        #pragma unroll
        for (int off = 1; off < 4; off <<= 1) {
            int y = __shfl_up_sync(0xfu, xw, off);
            if (lane >= off) xw += y;
        }
        wsum[lane] = xw - w;
    }
    __syncthreads();
    if (t < NB_SCAN) g_bsum[t] = wsum[warp] + x - v;  // exclusive
}

// add block offsets; init fill cursors
__global__ void scan3_kernel() {
    int i = blockIdx.x * blockDim.x + threadIdx.x;
    if (i < NN) {
        int o = g_off[i] + g_bsum[i >> 9];  // 512 = 2^9
        g_off[i] = o;
        g_pos[i] = o;
    }
}

__global__ void fill_kernel(const int* __restrict__ src, const int* __restrict__ dst, int E) {
    int e = blockIdx.x * blockDim.x + threadIdx.x;
    if (e < E) {
        int p = atomicAdd(&g_pos[dst[e]], 1);
        g_srcs[p] = src[e];
    }
}

// ---------------------------------------------------------------------------
// Segmented reduce: one warp per node; fp16 gather, fp32 accumulate;
// fused bias + relu epilogue. Unroll-2 for MLP.
// Each lane owns cols 4*lane .. 4*lane+3 (one uint2 = 4 halves per row).
// ---------------------------------------------------------------------------
__global__ __launch_bounds__(256)
void reduce_kernel(const float* __restrict__ b, float* __restrict__ out) {
    const int n = (int)((blockIdx.x * (unsigned)blockDim.x + threadIdx.x) >> 5);
    if (n >= NN) return;
    const int lane = threadIdx.x & 31;

    const int beg = g_off[n];
    const int deg = g_cnt[n];

    float4 acc = make_float4(0.f, 0.f, 0.f, 0.f);

    int i = 0;
    for (; i + 2 <= deg; i += 2) {
        const int s0 = __ldg(&g_srcs[beg + i]);
        const int s1 = __ldg(&g_srcs[beg + i + 1]);
        const uint2 v0 = __ldg((const uint2*)(g_hw + (size_t)s0 * MM) + lane);
        const uint2 v1 = __ldg((const uint2*)(g_hw + (size_t)s1 * MM) + lane);
        const float2 a0 = __half22float2(*(const __half2*)&v0.x);
        const float2 a1 = __half22float2(*(const __half2*)&v0.y);
        const float2 b0 = __half22float2(*(const __half2*)&v1.x);
        const float2 b1 = __half22float2(*(const __half2*)&v1.y);
        acc.x += a0.x + b0.x;
        acc.y += a0.y + b0.y;
        acc.z += a1.x + b1.x;
        acc.w += a1.y + b1.y;
    }
    if (i < deg) {
        const int s0 = __ldg(&g_srcs[beg + i]);
        const uint2 v0 = __ldg((const uint2*)(g_hw + (size_t)s0 * MM) + lane);
        const float2 a0 = __half22float2(*(const __half2*)&v0.x);
        const float2 a1 = __half22float2(*(const __half2*)&v0.y);
        acc.x += a0.x; acc.y += a0.y; acc.z += a1.x; acc.w += a1.y;
    }

    const float4 bv = __ldg((const float4*)b + lane);
    acc.x = fmaxf(acc.x + bv.x, 0.f);
    acc.y = fmaxf(acc.y + bv.y, 0.f);
    acc.z = fmaxf(acc.z + bv.z, 0.f);
    acc.w = fmaxf(acc.w + bv.w, 0.f);

    ((float4*)(out + (size_t)n * MM))[lane] = acc;
}

// ---------------------------------------------------------------------------
// Launch: h, W, b, src, dst  ->  out [N, 128] fp32
// ---------------------------------------------------------------------------
extern "C" void kernel_launch(void* const* d_in, const int* in_sizes, int n_in,
                              void* d_out, int out_size) {
    const float* h = (const float*)d_in[0];
    const float* W = (const float*)d_in[1];
    const float* b = (const float*)d_in[2];
    const int* src = (const int*)d_in[3];
    const int* dst = (const int*)d_in[4];
    float* out = (float*)d_out;

    const int E = in_sizes[3];

    static bool attr_set = false;
    if (!attr_set) {
        cudaFuncSetAttribute(gemm_kernel,
                             cudaFuncAttributeMaxDynamicSharedMemorySize,
                             128 * 128 * (int)sizeof(ull));
        attr_set = true;
    }

    // 1) hw = h @ W (fp16 out)
    gemm_kernel<<<(NN + 127) / 128, 512, 128 * 128 * sizeof(ull)>>>(h, W);

    // 2) CSR build
    zero_cnt_kernel<<<(NN + 255) / 256, 256>>>();
    hist_kernel<<<(E + 255) / 256, 256>>>(dst, E);
    scan1_kernel<<<NB_SCAN, SCAN_B>>>();
    scan2_kernel<<<1, 128>>>();
    scan3_kernel<<<(NN + 255) / 256, 256>>>();
    fill_kernel<<<(E + 255) / 256, 256>>>(src, dst, E);

    // 3) segmented reduce + bias + relu (one warp per node)
    {
        const long long threads = (long long)NN * 32;
        reduce_kernel<<<(int)((threads + 255) / 256), 256>>>(b, out);
    }
}

// round 5
// speedup vs baseline: 1.5892x; 1.0892x over previous
#include <cuda_runtime.h>
#include <cuda_fp16.h>
#include <cstdint>

typedef unsigned long long ull;

// Problem shape (fixed by the dataset)
#define NN 50000     // nodes
#define KK 256       // in feats
#define MM 128       // out feats
#define EE 800000    // edges

#define SCAN_B 512
#define NB_SCAN ((NN + SCAN_B - 1) / SCAN_B)   // 98

// Static scratch (no allocs allowed)
__device__ __half g_hw[(size_t)NN * MM];  // h @ W in fp16 (12.8 MB, L2-resident)
__device__ int   g_cnt[NN];               // degree histogram
__device__ int   g_off[NN];               // CSR exclusive offsets
__device__ int   g_pos[NN];               // fill cursors
__device__ int   g_bsum[NB_SCAN + 32];    // scan block sums
__device__ int   g_srcs[EE];              // src ids grouped by dst

// ---------------------------------------------------------------------------
// Kernel 1: hw = h @ W via tensor cores (mma.sync m16n8k8 tf32).
// Precision: W split into tf32 (hi, lo) pairs => A(rna) * (Whi + Wlo) = A * W
// exactly in fp32 accumulation; only h's tf32 rounding error remains.
//
// CTA tile: 128 rows x 128 cols, K chunked by 64.
// SMEM: hs[128][68]  (fp32 h chunk, pad 68 => conflict-free A-frag LDS)
//       Wp[64][132]  (float2 (hi,lo) pairs, pad 132 => conflict-free LDS.64)
// 8 warps x 16 rows each; 16 n-tiles of 8 cols; D accum = 64 fp32 regs/thread.
// ---------------------------------------------------------------------------
#define HS_PAD 68
#define WP_PAD 132
#define HS_FLOATS (128 * HS_PAD)               // 8704
#define GEMM_SMEM (HS_FLOATS * 4 + 64 * WP_PAD * 8)  // 34816 + 67584 = 102400

__device__ __forceinline__ unsigned f2tf32(float x) {
    unsigned r;
    asm("cvt.rna.tf32.f32 %0, %1;" : "=r"(r) : "f"(x));
    return r;
}

__global__ __launch_bounds__(256)
void gemm_kernel(const float* __restrict__ h, const float* __restrict__ W) {
    extern __shared__ float smem[];
    float*  hs = smem;                         // [128][HS_PAD]
    float2* Wp = (float2*)(smem + HS_FLOATS);  // [64][WP_PAD]

    const int tid  = threadIdx.x;
    const int warp = tid >> 5;
    const int lane = tid & 31;
    const int q    = lane & 3;    // k-offset within frag
    const int l4   = lane >> 2;   // row/col group

    const int blk_row0 = blockIdx.x * 128;

    float d[16][4];
    #pragma unroll
    for (int nt = 0; nt < 16; nt++)
        #pragma unroll
        for (int j = 0; j < 4; j++) d[nt][j] = 0.f;

    for (int kc = 0; kc < 4; kc++) {           // 4 chunks of K=64
        if (kc) __syncthreads();

        // stage W chunk: hi/lo tf32 split pairs
        for (int idx = tid; idx < 64 * 128; idx += 256) {
            const int kr = idx >> 7;
            const int c  = idx & 127;
            const float w = W[(kc * 64 + kr) * MM + c];
            const unsigned hib = f2tf32(w);
            const float hif = __uint_as_float(hib);
            const float lof = __uint_as_float(f2tf32(w - hif));
            Wp[kr * WP_PAD + c] = make_float2(hif, lof);
        }
        // stage h chunk: 128 rows x 64 cols (float4 coalesced)
        for (int i = tid; i < 128 * 16; i += 256) {
            const int row = i >> 4;
            const int f4  = i & 15;
            int rg = blk_row0 + row;
            if (rg >= NN) rg = NN - 1;
            const float4 v = __ldg((const float4*)(h + (size_t)rg * KK + kc * 64) + f4);
            ((float4*)(hs + row * HS_PAD))[f4] = v;
        }
        __syncthreads();

        #pragma unroll
        for (int ks = 0; ks < 8; ks++) {       // 8 k-steps of 8
            const int k8 = ks * 8;
            const int ar = warp * 16 + l4;
            const unsigned a0 = f2tf32(hs[(ar    ) * HS_PAD + k8 + q    ]);
            const unsigned a1 = f2tf32(hs[(ar + 8) * HS_PAD + k8 + q    ]);
            const unsigned a2 = f2tf32(hs[(ar    ) * HS_PAD + k8 + q + 4]);
            const unsigned a3 = f2tf32(hs[(ar + 8) * HS_PAD + k8 + q + 4]);

            #pragma unroll
            for (int nt = 0; nt < 16; nt++) {
                const float2 p0 = Wp[(k8 + q    ) * WP_PAD + nt * 8 + l4];
                const float2 p1 = Wp[(k8 + q + 4) * WP_PAD + nt * 8 + l4];
                asm("mma.sync.aligned.m16n8k8.row.col.f32.tf32.tf32.f32 "
                    "{%0,%1,%2,%3}, {%4,%5,%6,%7}, {%8,%9}, {%0,%1,%2,%3};"
                    : "+f"(d[nt][0]), "+f"(d[nt][1]), "+f"(d[nt][2]), "+f"(d[nt][3])
                    : "r"(a0), "r"(a1), "r"(a2), "r"(a3),
                      "r"(__float_as_uint(p0.x)), "r"(__float_as_uint(p1.x)));
                asm("mma.sync.aligned.m16n8k8.row.col.f32.tf32.tf32.f32 "
                    "{%0,%1,%2,%3}, {%4,%5,%6,%7}, {%8,%9}, {%0,%1,%2,%3};"
                    : "+f"(d[nt][0]), "+f"(d[nt][1]), "+f"(d[nt][2]), "+f"(d[nt][3])
                    : "r"(a0), "r"(a1), "r"(a2), "r"(a3),
                      "r"(__float_as_uint(p0.y)), "r"(__float_as_uint(p1.y)));
            }
        }
    }

    // epilogue: fp16 store. D layout: d0,d1 at (l4, 2q..2q+1), d2,d3 at (l4+8, ..)
    const int r0 = blk_row0 + warp * 16 + l4;
    #pragma unroll
    for (int nt = 0; nt < 16; nt++) {
        const int col = nt * 8 + q * 2;
        if (r0 < NN)
            *(__half2*)(g_hw + (size_t)r0 * MM + col) = __floats2half2_rn(d[nt][0], d[nt][1]);
        if (r0 + 8 < NN)
            *(__half2*)(g_hw + (size_t)(r0 + 8) * MM + col) = __floats2half2_rn(d[nt][2], d[nt][3]);
    }
}

// ---------------------------------------------------------------------------
// CSR build kernels
// ---------------------------------------------------------------------------
__global__ void zero_cnt_kernel() {
    int i = blockIdx.x * blockDim.x + threadIdx.x;
    if (i < NN) g_cnt[i] = 0;
}

__global__ void hist_kernel(const int* __restrict__ dst, int E) {
    int e = blockIdx.x * blockDim.x + threadIdx.x;
    if (e < E) atomicAdd(&g_cnt[dst[e]], 1);
}

// warp-shuffle exclusive scan of 512 counts per block; write block total
__global__ __launch_bounds__(SCAN_B)
void scan1_kernel() {
    __shared__ int wsum[16];
    const int t = threadIdx.x;
    const int lane = t & 31;
    const int warp = t >> 5;
    const int i = blockIdx.x * SCAN_B + t;
    const int v = (i < NN) ? g_cnt[i] : 0;

    int x = v;
    #pragma unroll
    for (int off = 1; off < 32; off <<= 1) {
        int y = __shfl_up_sync(0xffffffffu, x, off);
        if (lane >= off) x += y;
    }
    if (lane == 31) wsum[warp] = x;
    __syncthreads();
    if (warp == 0 && lane < 16) {
        int w = wsum[lane];
        int xw = w;
        #pragma unroll
        for (int off = 1; off < 16; off <<= 1) {
            int y = __shfl_up_sync(0xffffu, xw, off);
            if (lane >= off) xw += y;
        }
        wsum[lane] = xw - w;
    }
    __syncthreads();
    const int base = wsum[warp];
    if (i < NN) g_off[i] = base + x - v;
    if (t == SCAN_B - 1) g_bsum[blockIdx.x] = base + x;
}

// exclusive scan of NB_SCAN (=98) block sums
__global__ __launch_bounds__(128)
void scan2_kernel() {
    __shared__ int wsum[4];
    const int t = threadIdx.x;
    const int lane = t & 31;
    const int warp = t >> 5;
    const int v = (t < NB_SCAN) ? g_bsum[t] : 0;

    int x = v;
    #pragma unroll
    for (int off = 1; off < 32; off <<= 1) {
        int y = __shfl_up_sync(0xffffffffu, x, off);
        if (lane >= off) x += y;
    }
    if (lane == 31) wsum[warp] = x;
    __syncthreads();
    if (warp == 0 && lane < 4) {
        int w = wsum[lane];
        int xw = w;
        #pragma unroll
        for (int off = 1; off < 4; off <<= 1) {
            int y = __shfl_up_sync(0xfu, xw, off);
            if (lane >= off) xw += y;
        }
        wsum[lane] = xw - w;
    }
    __syncthreads();
    if (t < NB_SCAN) g_bsum[t] = wsum[warp] + x - v;
}

// add block offsets; init fill cursors
__global__ void scan3_kernel() {
    int i = blockIdx.x * blockDim.x + threadIdx.x;
    if (i < NN) {
        int o = g_off[i] + g_bsum[i >> 9];
        g_off[i] = o;
        g_pos[i] = o;
    }
}

__global__ void fill_kernel(const int* __restrict__ src, const int* __restrict__ dst, int E) {
    int e = blockIdx.x * blockDim.x + threadIdx.x;
    if (e < E) {
        int p = atomicAdd(&g_pos[dst[e]], 1);
        g_srcs[p] = src[e];
    }
}

// ---------------------------------------------------------------------------
// Segmented reduce: one warp per node; fp16 gather, fp32 accumulate;
// fused bias + relu epilogue.
// ---------------------------------------------------------------------------
__global__ __launch_bounds__(256)
void reduce_kernel(const float* __restrict__ b, float* __restrict__ out) {
    const int n = (int)((blockIdx.x * (unsigned)blockDim.x + threadIdx.x) >> 5);
    if (n >= NN) return;
    const int lane = threadIdx.x & 31;

    const int beg = g_off[n];
    const int deg = g_cnt[n];

    float4 acc = make_float4(0.f, 0.f, 0.f, 0.f);

    int i = 0;
    for (; i + 2 <= deg; i += 2) {
        const int s0 = __ldg(&g_srcs[beg + i]);
        const int s1 = __ldg(&g_srcs[beg + i + 1]);
        const uint2 v0 = __ldg((const uint2*)(g_hw + (size_t)s0 * MM) + lane);
        const uint2 v1 = __ldg((const uint2*)(g_hw + (size_t)s1 * MM) + lane);
        const float2 a0 = __half22float2(*(const __half2*)&v0.x);
        const float2 a1 = __half22float2(*(const __half2*)&v0.y);
        const float2 b0 = __half22float2(*(const __half2*)&v1.x);
        const float2 b1 = __half22float2(*(const __half2*)&v1.y);
        acc.x += a0.x + b0.x;
        acc.y += a0.y + b0.y;
        acc.z += a1.x + b1.x;
        acc.w += a1.y + b1.y;
    }
    if (i < deg) {
        const int s0 = __ldg(&g_srcs[beg + i]);
        const uint2 v0 = __ldg((const uint2*)(g_hw + (size_t)s0 * MM) + lane);
        const float2 a0 = __half22float2(*(const __half2*)&v0.x);
        const float2 a1 = __half22float2(*(const __half2*)&v0.y);
        acc.x += a0.x; acc.y += a0.y; acc.z += a1.x; acc.w += a1.y;
    }

    const float4 bv = __ldg((const float4*)b + lane);
    acc.x = fmaxf(acc.x + bv.x, 0.f);
    acc.y = fmaxf(acc.y + bv.y, 0.f);
    acc.z = fmaxf(acc.z + bv.z, 0.f);
    acc.w = fmaxf(acc.w + bv.w, 0.f);

    ((float4*)(out + (size_t)n * MM))[lane] = acc;
}

// ---------------------------------------------------------------------------
// Launch: h, W, b, src, dst  ->  out [N, 128] fp32
// ---------------------------------------------------------------------------
extern "C" void kernel_launch(void* const* d_in, const int* in_sizes, int n_in,
                              void* d_out, int out_size) {
    const float* h = (const float*)d_in[0];
    const float* W = (const float*)d_in[1];
    const float* b = (const float*)d_in[2];
    const int* src = (const int*)d_in[3];
    const int* dst = (const int*)d_in[4];
    float* out = (float*)d_out;

    const int E = in_sizes[3];

    static bool attr_set = false;
    if (!attr_set) {
        cudaFuncSetAttribute(gemm_kernel,
                             cudaFuncAttributeMaxDynamicSharedMemorySize,
                             GEMM_SMEM);
        attr_set = true;
    }

    // 1) hw = h @ W (tensor cores, fp16 out)
    gemm_kernel<<<(NN + 127) / 128, 256, GEMM_SMEM>>>(h, W);

    // 2) CSR build
    zero_cnt_kernel<<<(NN + 255) / 256, 256>>>();
    hist_kernel<<<(E + 255) / 256, 256>>>(dst, E);
    scan1_kernel<<<NB_SCAN, SCAN_B>>>();
    scan2_kernel<<<1, 128>>>();
    scan3_kernel<<<(NN + 255) / 256, 256>>>();
    fill_kernel<<<(E + 255) / 256, 256>>>(src, dst, E);

    // 3) segmented reduce + bias + relu (one warp per node)
    {
        const long long threads = (long long)NN * 32;
        reduce_kernel<<<(int)((threads + 255) / 256), 256>>>(b, out);
    }
}